// round 5
// baseline (speedup 1.0000x reference)
#include <cuda_runtime.h>
#include <cuda_bf16.h>
#include <math.h>

// Problem constants
#define B_    2
#define S_    1024
#define HID_  2048
#define HQ_   32
#define HKV_  8
#define HD_   64
#define MTOK  (B_ * S_)          // 2048 tokens
#define NREP  (HQ_ / HKV_)       // 4

// Scratch (allocation-free rule: __device__ globals)
__device__ float g_q[MTOK * HID_];          // 16 MB
__device__ float g_k[MTOK * HKV_ * HD_];    // 4 MB
__device__ float g_v[MTOK * HKV_ * HD_];    // 4 MB
__device__ float g_attn[MTOK * HID_];       // 16 MB

// ---------------------------------------------------------------------------
// SGEMM: C[M,N] = A[M,K] @ B[K,N], row-major, fp32.
// 128x128 tile, BK=8, 256 threads, 8x8 per-thread microtile.
// M,N,K all multiples of tile dims here (no bounds checks).
// ---------------------------------------------------------------------------
#define BM 128
#define BN 128
#define BK 8
#define TM 8
#define TN 8

__global__ __launch_bounds__(256, 2)
void sgemm_kernel(const float* __restrict__ A, const float* __restrict__ Bm,
                  float* __restrict__ C, int M, int N, int K)
{
    __shared__ float As[BK][BM];   // transposed A tile
    __shared__ float Bs[BK][BN];

    const int bx = blockIdx.x;     // N dir
    const int by = blockIdx.y;     // M dir
    const int tid = threadIdx.x;
    const int tx = tid & 15;       // 0..15 (N dir)
    const int ty = tid >> 4;       // 0..15 (M dir)

    const float* Aptr = A + (size_t)by * BM * K;
    const float* Bptr = Bm + (size_t)bx * BN;

    // load indices
    const int arow = tid >> 1;            // 0..127
    const int acol = (tid & 1) * 4;       // 0 or 4
    const int brow = tid >> 5;            // 0..7
    const int bcol = (tid & 31) * 4;      // 0..124

    float acc[TM][TN];
    #pragma unroll
    for (int i = 0; i < TM; i++)
        #pragma unroll
        for (int j = 0; j < TN; j++) acc[i][j] = 0.f;

    for (int k0 = 0; k0 < K; k0 += BK) {
        float4 a4 = *(const float4*)(Aptr + (size_t)arow * K + k0 + acol);
        As[acol + 0][arow] = a4.x;
        As[acol + 1][arow] = a4.y;
        As[acol + 2][arow] = a4.z;
        As[acol + 3][arow] = a4.w;
        float4 b4 = *(const float4*)(Bptr + (size_t)(k0 + brow) * N + bcol);
        *(float4*)&Bs[brow][bcol] = b4;
        __syncthreads();

        #pragma unroll
        for (int kk = 0; kk < BK; kk++) {
            float a[TM], b[TN];
            *(float4*)&a[0] = *(const float4*)&As[kk][ty * TM + 0];
            *(float4*)&a[4] = *(const float4*)&As[kk][ty * TM + 4];
            *(float4*)&b[0] = *(const float4*)&Bs[kk][tx * TN + 0];
            *(float4*)&b[4] = *(const float4*)&Bs[kk][tx * TN + 4];
            #pragma unroll
            for (int i = 0; i < TM; i++)
                #pragma unroll
                for (int j = 0; j < TN; j++)
                    acc[i][j] += a[i] * b[j];
        }
        __syncthreads();
    }

    #pragma unroll
    for (int i = 0; i < TM; i++) {
        float* crow = C + (size_t)(by * BM + ty * TM + i) * N + bx * BN + tx * TN;
        *(float4*)(crow + 0) = *(float4*)&acc[i][0];
        *(float4*)(crow + 4) = *(float4*)&acc[i][4];
    }
}

// ---------------------------------------------------------------------------
// RoPE (in place). X: (MTOK, nheads, 64). One thread per (token, head, d<32).
// ---------------------------------------------------------------------------
__global__ void rope_kernel(float* __restrict__ X,
                            const float* __restrict__ cosT,
                            const float* __restrict__ sinT,
                            int nheads)
{
    int idx = blockIdx.x * blockDim.x + threadIdx.x;
    int total = MTOK * nheads * 32;
    if (idx >= total) return;
    int d  = idx & 31;
    int hh = (idx >> 5) % nheads;
    int t  = idx / (32 * nheads);
    int s  = t & (S_ - 1);

    float c  = __ldg(cosT + s * HD_ + d);      // cos[s,d] == cos[s,d+32]
    float sn = __ldg(sinT + s * HD_ + d);

    float* base = X + ((size_t)t * nheads + hh) * HD_;
    float x0 = base[d];
    float x1 = base[d + 32];
    base[d]      = x0 * c - x1 * sn;
    base[d + 32] = x1 * c + x0 * sn;
}

// ---------------------------------------------------------------------------
// Flash-style causal GQA attention.
// grid = (S/64, HQ, B), block = 64 threads. One q row per thread.
// Q in registers (64 f), K/V tiles in smem, scores via transposed smem tile.
// ---------------------------------------------------------------------------
__global__ __launch_bounds__(64)
void attn_kernel(const float* __restrict__ Q, const float* __restrict__ K,
                 const float* __restrict__ V, float* __restrict__ O)
{
    __shared__ float Ks[64][64];
    __shared__ float Vs[64][64];
    __shared__ float Ss[64][64];   // Ss[j][r] -> conflict-free per-thread column

    const int qb  = blockIdx.x;
    const int h   = blockIdx.y;
    const int b   = blockIdx.z;
    const int kvh = h >> 2;        // h / NREP
    const int tid = threadIdx.x;   // q row within tile

    const float scale = 0.125f;    // 1/sqrt(64)

    // Load own q row into registers
    const int tok = b * S_ + qb * 64 + tid;
    float q[64];
    {
        const float4* qp = (const float4*)(Q + (size_t)tok * HID_ + h * HD_);
        #pragma unroll
        for (int i = 0; i < 16; i++) {
            float4 t4 = qp[i];
            q[i * 4 + 0] = t4.x; q[i * 4 + 1] = t4.y;
            q[i * 4 + 2] = t4.z; q[i * 4 + 3] = t4.w;
        }
    }

    float acc[64];
    #pragma unroll
    for (int d = 0; d < 64; d++) acc[d] = 0.f;
    float m = -1e30f, l = 0.f;

    for (int kb = 0; kb <= qb; kb++) {
        // Stage K/V tiles (coalesced: consecutive threads -> consecutive d)
        for (int e = tid; e < 64 * 64; e += 64) {
            int r = e >> 6, d = e & 63;
            size_t gaddr = ((size_t)(b * S_ + kb * 64 + r) * HKV_ + kvh) * HD_ + d;
            Ks[r][d] = K[gaddr];
            Vs[r][d] = V[gaddr];
        }
        __syncthreads();

        const bool diag = (kb == qb);
        float mloc = -1e30f;
        // Phase 1: scores for all 64 keys
        #pragma unroll 4
        for (int j = 0; j < 64; j++) {
            float s;
            if (diag && j > tid) {
                s = -1e30f;
            } else {
                s = 0.f;
                #pragma unroll
                for (int d = 0; d < 64; d += 4) {
                    float4 k4 = *(const float4*)&Ks[j][d];
                    s += q[d] * k4.x + q[d + 1] * k4.y
                       + q[d + 2] * k4.z + q[d + 3] * k4.w;
                }
                s *= scale;
            }
            mloc = fmaxf(mloc, s);
            Ss[j][tid] = s;
        }

        float mnew = fmaxf(m, mloc);
        float corr = __expf(m - mnew);
        l *= corr;
        #pragma unroll
        for (int d = 0; d < 64; d++) acc[d] *= corr;

        // Phase 2: probs and PV accumulate
        #pragma unroll 2
        for (int j = 0; j < 64; j++) {
            float p = __expf(Ss[j][tid] - mnew);
            l += p;
            #pragma unroll
            for (int d = 0; d < 64; d += 4) {
                float4 v4 = *(const float4*)&Vs[j][d];
                acc[d]     += p * v4.x;
                acc[d + 1] += p * v4.y;
                acc[d + 2] += p * v4.z;
                acc[d + 3] += p * v4.w;
            }
        }
        m = mnew;
        __syncthreads();  // protect Ks/Vs before next stage
    }

    float inv = 1.f / l;
    float4* op = (float4*)(O + (size_t)tok * HID_ + h * HD_);
    #pragma unroll
    for (int i = 0; i < 16; i++) {
        float4 o4;
        o4.x = acc[i * 4 + 0] * inv;
        o4.y = acc[i * 4 + 1] * inv;
        o4.z = acc[i * 4 + 2] * inv;
        o4.w = acc[i * 4 + 3] * inv;
        op[i] = o4;
    }
}

// ---------------------------------------------------------------------------
// Launch
// inputs: 0=hidden (B,S,HID) 1=cos (S,64) 2=sin (S,64)
//         3=Wq (2048,2048) 4=Wk (2048,512) 5=Wv (2048,512) 6=Wo (2048,2048)
// out: (B,S,HID) fp32
// ---------------------------------------------------------------------------
extern "C" void kernel_launch(void* const* d_in, const int* in_sizes, int n_in,
                              void* d_out, int out_size)
{
    const float* hid  = (const float*)d_in[0];
    const float* cosT = (const float*)d_in[1];
    const float* sinT = (const float*)d_in[2];
    const float* Wq   = (const float*)d_in[3];
    const float* Wk   = (const float*)d_in[4];
    const float* Wv   = (const float*)d_in[5];
    const float* Wo   = (const float*)d_in[6];
    float* out = (float*)d_out;

    float *q_p, *k_p, *v_p, *attn_p;
    cudaGetSymbolAddress((void**)&q_p,    g_q);
    cudaGetSymbolAddress((void**)&k_p,    g_k);
    cudaGetSymbolAddress((void**)&v_p,    g_v);
    cudaGetSymbolAddress((void**)&attn_p, g_attn);

    // Projections
    {
        dim3 gq(HID_ / BN, MTOK / BM);
        sgemm_kernel<<<gq, 256>>>(hid, Wq, q_p, MTOK, HID_, HID_);
        dim3 gkv((HKV_ * HD_) / BN, MTOK / BM);
        sgemm_kernel<<<gkv, 256>>>(hid, Wk, k_p, MTOK, HKV_ * HD_, HID_);
        sgemm_kernel<<<gkv, 256>>>(hid, Wv, v_p, MTOK, HKV_ * HD_, HID_);
    }

    // RoPE
    {
        int totq = MTOK * HQ_ * 32;
        rope_kernel<<<(totq + 255) / 256, 256>>>(q_p, cosT, sinT, HQ_);
        int totk = MTOK * HKV_ * 32;
        rope_kernel<<<(totk + 255) / 256, 256>>>(k_p, cosT, sinT, HKV_);
    }

    // Attention
    {
        dim3 ga(S_ / 64, HQ_, B_);
        attn_kernel<<<ga, 64>>>(q_p, k_p, v_p, attn_p);
    }

    // Output projection
    {
        dim3 go(HID_ / BN, MTOK / BM);
        sgemm_kernel<<<go, 256>>>(attn_p, Wo, out, MTOK, HID_, HID_);
    }
}

// round 6
// speedup vs baseline: 2.1048x; 2.1048x over previous
#include <cuda_runtime.h>
#include <cuda_bf16.h>
#include <math.h>

// Problem constants
#define B_    2
#define S_    1024
#define HID_  2048
#define HQ_   32
#define HKV_  8
#define HD_   64
#define MTOK  (B_ * S_)          // 2048 tokens
#define NREP  (HQ_ / HKV_)       // 4

// Scratch (allocation-free rule: __device__ globals)
__device__ float g_q[MTOK * HID_];          // 16 MB
__device__ float g_k[MTOK * HKV_ * HD_];    // 4 MB
__device__ float g_v[MTOK * HKV_ * HD_];    // 4 MB
__device__ float g_attn[MTOK * HID_];       // 16 MB

// ---------------------------------------------------------------------------
// tf32 tensor-core GEMM. C[M,N] = A[M,K] @ B[K,N], row-major fp32 in/out.
// CTA tile 128x128, BK=32, 256 threads (8 warps, 2x4), warp tile 64x32.
// Smem is k-major with stride 136 floats: bank = (8k + m) % 32 -> all
// fragment LDS conflict-free. Fused QKV via blockIdx.x split.
// ---------------------------------------------------------------------------
#define BKT 32
#define SST 136

__device__ __forceinline__ unsigned f2tf32(float x) {
    unsigned r;
    asm("cvt.rna.tf32.f32 %0, %1;" : "=r"(r) : "f"(x));
    return r;
}

__global__ __launch_bounds__(256, 2)
void mma_gemm_qkv(const float* __restrict__ A,
                  const float* __restrict__ Wq, const float* __restrict__ Wk,
                  const float* __restrict__ Wv,
                  float* __restrict__ Cq, float* __restrict__ Ck,
                  float* __restrict__ Cv)
{
    __shared__ unsigned As[BKT][SST];
    __shared__ unsigned Bs[BKT][SST];

    const int bx = blockIdx.x;
    const int by = blockIdx.y;

    const float* Bp; float* Cp; int Nb, n0;
    if (bx < 16)      { Bp = Wq; Cp = Cq; Nb = 2048; n0 = bx * 128; }
    else if (bx < 20) { Bp = Wk; Cp = Ck; Nb = 512;  n0 = (bx - 16) * 128; }
    else              { Bp = Wv; Cp = Cv; Nb = 512;  n0 = (bx - 20) * 128; }

    const int tid  = threadIdx.x;
    const int wid  = tid >> 5;
    const int lane = tid & 31;
    const int wm   = wid >> 2;       // 0..1
    const int wn   = wid & 3;        // 0..3
    const int g    = lane >> 2;      // groupID 0..7
    const int tg   = lane & 3;       // threadID_in_group 0..3
    const int m0   = by * 128;

    float acc[4][4][4];
    #pragma unroll
    for (int mi = 0; mi < 4; mi++)
        #pragma unroll
        for (int ni = 0; ni < 4; ni++)
            #pragma unroll
            for (int c = 0; c < 4; c++) acc[mi][ni][c] = 0.f;

    // global-load indices
    const int arow  = tid >> 1;            // 0..127
    const int acol  = (tid & 1) * 16;      // 0 or 16
    const int bkrow = tid >> 3;            // 0..31
    const int bncol = (tid & 7) * 4;       // 0..28

    for (int k0 = 0; k0 < HID_; k0 += BKT) {
        // Stage A 128x32 (transpose into k-major)
        #pragma unroll
        for (int j = 0; j < 4; j++) {
            float4 a4 = *(const float4*)(A + (size_t)(m0 + arow) * HID_ + k0 + acol + j * 4);
            As[acol + j * 4 + 0][arow] = f2tf32(a4.x);
            As[acol + j * 4 + 1][arow] = f2tf32(a4.y);
            As[acol + j * 4 + 2][arow] = f2tf32(a4.z);
            As[acol + j * 4 + 3][arow] = f2tf32(a4.w);
        }
        // Stage B 32x128 (already k-major rows)
        #pragma unroll
        for (int j = 0; j < 4; j++) {
            float4 b4 = *(const float4*)(Bp + (size_t)(k0 + bkrow) * Nb + n0 + bncol + j * 32);
            unsigned* dst = &Bs[bkrow][bncol + j * 32];
            dst[0] = f2tf32(b4.x);
            dst[1] = f2tf32(b4.y);
            dst[2] = f2tf32(b4.z);
            dst[3] = f2tf32(b4.w);
        }
        __syncthreads();

        #pragma unroll
        for (int ks = 0; ks < 4; ks++) {
            unsigned afr[4][4], bfr[4][2];
            #pragma unroll
            for (int mi = 0; mi < 4; mi++) {
                int mb = wm * 64 + mi * 16;
                afr[mi][0] = As[ks * 8 + tg    ][mb + g];
                afr[mi][1] = As[ks * 8 + tg    ][mb + g + 8];
                afr[mi][2] = As[ks * 8 + tg + 4][mb + g];
                afr[mi][3] = As[ks * 8 + tg + 4][mb + g + 8];
            }
            #pragma unroll
            for (int ni = 0; ni < 4; ni++) {
                int nb = wn * 32 + ni * 8;
                bfr[ni][0] = Bs[ks * 8 + tg    ][nb + g];
                bfr[ni][1] = Bs[ks * 8 + tg + 4][nb + g];
            }
            #pragma unroll
            for (int mi = 0; mi < 4; mi++)
                #pragma unroll
                for (int ni = 0; ni < 4; ni++)
                    asm volatile(
                        "mma.sync.aligned.m16n8k8.row.col.f32.tf32.tf32.f32 "
                        "{%0,%1,%2,%3}, {%4,%5,%6,%7}, {%8,%9}, {%0,%1,%2,%3};"
                        : "+f"(acc[mi][ni][0]), "+f"(acc[mi][ni][1]),
                          "+f"(acc[mi][ni][2]), "+f"(acc[mi][ni][3])
                        : "r"(afr[mi][0]), "r"(afr[mi][1]),
                          "r"(afr[mi][2]), "r"(afr[mi][3]),
                          "r"(bfr[ni][0]), "r"(bfr[ni][1]));
        }
        __syncthreads();
    }

    // Writeback
    #pragma unroll
    for (int mi = 0; mi < 4; mi++) {
        int row0 = m0 + wm * 64 + mi * 16 + g;
        #pragma unroll
        for (int ni = 0; ni < 4; ni++) {
            int col = n0 + wn * 32 + ni * 8 + tg * 2;
            *(float2*)(Cp + (size_t)row0 * Nb + col) =
                make_float2(acc[mi][ni][0], acc[mi][ni][1]);
            *(float2*)(Cp + (size_t)(row0 + 8) * Nb + col) =
                make_float2(acc[mi][ni][2], acc[mi][ni][3]);
        }
    }
}

// ---------------------------------------------------------------------------
// RoPE (in place). X: (MTOK, nheads, 64). One thread per (token, head, d<32).
// ---------------------------------------------------------------------------
__global__ void rope_kernel(float* __restrict__ X,
                            const float* __restrict__ cosT,
                            const float* __restrict__ sinT,
                            int nheads)
{
    int idx = blockIdx.x * blockDim.x + threadIdx.x;
    int total = MTOK * nheads * 32;
    if (idx >= total) return;
    int d  = idx & 31;
    int hh = (idx >> 5) % nheads;
    int t  = idx / (32 * nheads);
    int s  = t & (S_ - 1);

    float c  = __ldg(cosT + s * HD_ + d);
    float sn = __ldg(sinT + s * HD_ + d);

    float* base = X + ((size_t)t * nheads + hh) * HD_;
    float x0 = base[d];
    float x1 = base[d + 32];
    base[d]      = x0 * c - x1 * sn;
    base[d + 32] = x1 * c + x0 * sn;
}

// ---------------------------------------------------------------------------
// Flash-style causal GQA attention (fp32). grid=(S/64, HQ, B), 64 threads.
// ---------------------------------------------------------------------------
__global__ __launch_bounds__(64)
void attn_kernel(const float* __restrict__ Q, const float* __restrict__ K,
                 const float* __restrict__ V, float* __restrict__ O)
{
    __shared__ float Ks[64][64];
    __shared__ float Vs[64][64];
    __shared__ float Ss[64][64];

    const int qb  = blockIdx.x;
    const int h   = blockIdx.y;
    const int b   = blockIdx.z;
    const int kvh = h >> 2;
    const int tid = threadIdx.x;

    const float scale = 0.125f;

    const int tok = b * S_ + qb * 64 + tid;
    float q[64];
    {
        const float4* qp = (const float4*)(Q + (size_t)tok * HID_ + h * HD_);
        #pragma unroll
        for (int i = 0; i < 16; i++) {
            float4 t4 = qp[i];
            q[i * 4 + 0] = t4.x; q[i * 4 + 1] = t4.y;
            q[i * 4 + 2] = t4.z; q[i * 4 + 3] = t4.w;
        }
    }

    float acc[64];
    #pragma unroll
    for (int d = 0; d < 64; d++) acc[d] = 0.f;
    float m = -1e30f, l = 0.f;

    for (int kb = 0; kb <= qb; kb++) {
        for (int e = tid; e < 64 * 64; e += 64) {
            int r = e >> 6, d = e & 63;
            size_t gaddr = ((size_t)(b * S_ + kb * 64 + r) * HKV_ + kvh) * HD_ + d;
            Ks[r][d] = K[gaddr];
            Vs[r][d] = V[gaddr];
        }
        __syncthreads();

        const bool diag = (kb == qb);
        float mloc = -1e30f;
        #pragma unroll 4
        for (int j = 0; j < 64; j++) {
            float s;
            if (diag && j > tid) {
                s = -1e30f;
            } else {
                s = 0.f;
                #pragma unroll
                for (int d = 0; d < 64; d += 4) {
                    float4 k4 = *(const float4*)&Ks[j][d];
                    s += q[d] * k4.x + q[d + 1] * k4.y
                       + q[d + 2] * k4.z + q[d + 3] * k4.w;
                }
                s *= scale;
            }
            mloc = fmaxf(mloc, s);
            Ss[j][tid] = s;
        }

        float mnew = fmaxf(m, mloc);
        float corr = __expf(m - mnew);
        l *= corr;
        #pragma unroll
        for (int d = 0; d < 64; d++) acc[d] *= corr;

        #pragma unroll 2
        for (int j = 0; j < 64; j++) {
            float p = __expf(Ss[j][tid] - mnew);
            l += p;
            #pragma unroll
            for (int d = 0; d < 64; d += 4) {
                float4 v4 = *(const float4*)&Vs[j][d];
                acc[d]     += p * v4.x;
                acc[d + 1] += p * v4.y;
                acc[d + 2] += p * v4.z;
                acc[d + 3] += p * v4.w;
            }
        }
        m = mnew;
        __syncthreads();
    }

    float inv = 1.f / l;
    float4* op = (float4*)(O + (size_t)tok * HID_ + h * HD_);
    #pragma unroll
    for (int i = 0; i < 16; i++) {
        float4 o4;
        o4.x = acc[i * 4 + 0] * inv;
        o4.y = acc[i * 4 + 1] * inv;
        o4.z = acc[i * 4 + 2] * inv;
        o4.w = acc[i * 4 + 3] * inv;
        op[i] = o4;
    }
}

// ---------------------------------------------------------------------------
// Launch
// ---------------------------------------------------------------------------
extern "C" void kernel_launch(void* const* d_in, const int* in_sizes, int n_in,
                              void* d_out, int out_size)
{
    const float* hid  = (const float*)d_in[0];
    const float* cosT = (const float*)d_in[1];
    const float* sinT = (const float*)d_in[2];
    const float* Wq   = (const float*)d_in[3];
    const float* Wk   = (const float*)d_in[4];
    const float* Wv   = (const float*)d_in[5];
    const float* Wo   = (const float*)d_in[6];
    float* out = (float*)d_out;

    float *q_p, *k_p, *v_p, *attn_p;
    cudaGetSymbolAddress((void**)&q_p,    g_q);
    cudaGetSymbolAddress((void**)&k_p,    g_k);
    cudaGetSymbolAddress((void**)&v_p,    g_v);
    cudaGetSymbolAddress((void**)&attn_p, g_attn);

    // Fused QKV projection (tf32 tensor cores)
    {
        dim3 g(24, 16);
        mma_gemm_qkv<<<g, 256>>>(hid, Wq, Wk, Wv, q_p, k_p, v_p);
    }

    // RoPE
    {
        int totq = MTOK * HQ_ * 32;
        rope_kernel<<<(totq + 255) / 256, 256>>>(q_p, cosT, sinT, HQ_);
        int totk = MTOK * HKV_ * 32;
        rope_kernel<<<(totk + 255) / 256, 256>>>(k_p, cosT, sinT, HKV_);
    }

    // Attention
    {
        dim3 ga(S_ / 64, HQ_, B_);
        attn_kernel<<<ga, 64>>>(q_p, k_p, v_p, attn_p);
    }

    // Output projection (same kernel, Q-path only)
    {
        dim3 go(16, 16);
        mma_gemm_qkv<<<go, 256>>>(attn_p, Wo, Wo, Wo, out, out, out);
    }
}

// round 8
// speedup vs baseline: 3.6371x; 1.7280x over previous
#include <cuda_runtime.h>
#include <cuda_bf16.h>
#include <math.h>

// Problem constants
#define B_    2
#define S_    1024
#define HID_  2048
#define HQ_   32
#define HKV_  8
#define HD_   64
#define MTOK  (B_ * S_)          // 2048 tokens
#define NREP  (HQ_ / HKV_)       // 4

// Scratch (allocation-free rule: __device__ globals)
__device__ float g_q[MTOK * HID_];          // 16 MB
__device__ float g_k[MTOK * HKV_ * HD_];    // 4 MB
__device__ float g_v[MTOK * HKV_ * HD_];    // 4 MB
__device__ float g_attn[MTOK * HID_];       // 16 MB

__device__ __forceinline__ unsigned f2tf32(float x) {
    unsigned r;
    asm("cvt.rna.tf32.f32 %0, %1;" : "=r"(r) : "f"(x));
    return r;
}

#define MMA_TF32(D, A, B0, B1)                                              \
    asm volatile(                                                           \
        "mma.sync.aligned.m16n8k8.row.col.f32.tf32.tf32.f32 "               \
        "{%0,%1,%2,%3}, {%4,%5,%6,%7}, {%8,%9}, {%0,%1,%2,%3};"             \
        : "+f"((D)[0]), "+f"((D)[1]), "+f"((D)[2]), "+f"((D)[3])            \
        : "r"((A)[0]), "r"((A)[1]), "r"((A)[2]), "r"((A)[3]),               \
          "r"(B0), "r"(B1))

// ---------------------------------------------------------------------------
// tf32 tensor-core GEMM. C[M,N] = A[M,K] @ B[K,N], row-major fp32 in/out.
// CTA tile 128x128, BK=32, 256 threads (8 warps, 2x4), warp tile 64x32.
// ---------------------------------------------------------------------------
#define BKT 32
#define SST 136

__global__ __launch_bounds__(256, 2)
void mma_gemm_qkv(const float* __restrict__ A,
                  const float* __restrict__ Wq, const float* __restrict__ Wk,
                  const float* __restrict__ Wv,
                  float* __restrict__ Cq, float* __restrict__ Ck,
                  float* __restrict__ Cv)
{
    __shared__ unsigned As[BKT][SST];
    __shared__ unsigned Bs[BKT][SST];

    const int bx = blockIdx.x;
    const int by = blockIdx.y;

    const float* Bp; float* Cp; int Nb, n0;
    if (bx < 16)      { Bp = Wq; Cp = Cq; Nb = 2048; n0 = bx * 128; }
    else if (bx < 20) { Bp = Wk; Cp = Ck; Nb = 512;  n0 = (bx - 16) * 128; }
    else              { Bp = Wv; Cp = Cv; Nb = 512;  n0 = (bx - 20) * 128; }

    const int tid  = threadIdx.x;
    const int wid  = tid >> 5;
    const int lane = tid & 31;
    const int wm   = wid >> 2;
    const int wn   = wid & 3;
    const int g    = lane >> 2;
    const int tg   = lane & 3;
    const int m0   = by * 128;

    float acc[4][4][4];
    #pragma unroll
    for (int mi = 0; mi < 4; mi++)
        #pragma unroll
        for (int ni = 0; ni < 4; ni++)
            #pragma unroll
            for (int c = 0; c < 4; c++) acc[mi][ni][c] = 0.f;

    const int arow  = tid >> 1;
    const int acol  = (tid & 1) * 16;
    const int bkrow = tid >> 3;
    const int bncol = (tid & 7) * 4;

    for (int k0 = 0; k0 < HID_; k0 += BKT) {
        #pragma unroll
        for (int j = 0; j < 4; j++) {
            float4 a4 = *(const float4*)(A + (size_t)(m0 + arow) * HID_ + k0 + acol + j * 4);
            As[acol + j * 4 + 0][arow] = f2tf32(a4.x);
            As[acol + j * 4 + 1][arow] = f2tf32(a4.y);
            As[acol + j * 4 + 2][arow] = f2tf32(a4.z);
            As[acol + j * 4 + 3][arow] = f2tf32(a4.w);
        }
        #pragma unroll
        for (int j = 0; j < 4; j++) {
            float4 b4 = *(const float4*)(Bp + (size_t)(k0 + bkrow) * Nb + n0 + bncol + j * 32);
            unsigned* dst = &Bs[bkrow][bncol + j * 32];
            dst[0] = f2tf32(b4.x);
            dst[1] = f2tf32(b4.y);
            dst[2] = f2tf32(b4.z);
            dst[3] = f2tf32(b4.w);
        }
        __syncthreads();

        #pragma unroll
        for (int ks = 0; ks < 4; ks++) {
            unsigned afr[4][4], bfr[4][2];
            #pragma unroll
            for (int mi = 0; mi < 4; mi++) {
                int mb = wm * 64 + mi * 16;
                afr[mi][0] = As[ks * 8 + tg    ][mb + g];
                afr[mi][1] = As[ks * 8 + tg    ][mb + g + 8];
                afr[mi][2] = As[ks * 8 + tg + 4][mb + g];
                afr[mi][3] = As[ks * 8 + tg + 4][mb + g + 8];
            }
            #pragma unroll
            for (int ni = 0; ni < 4; ni++) {
                int nb = wn * 32 + ni * 8;
                bfr[ni][0] = Bs[ks * 8 + tg    ][nb + g];
                bfr[ni][1] = Bs[ks * 8 + tg + 4][nb + g];
            }
            #pragma unroll
            for (int mi = 0; mi < 4; mi++)
                #pragma unroll
                for (int ni = 0; ni < 4; ni++)
                    MMA_TF32(acc[mi][ni], afr[mi], bfr[ni][0], bfr[ni][1]);
        }
        __syncthreads();
    }

    #pragma unroll
    for (int mi = 0; mi < 4; mi++) {
        int row0 = m0 + wm * 64 + mi * 16 + g;
        #pragma unroll
        for (int ni = 0; ni < 4; ni++) {
            int col = n0 + wn * 32 + ni * 8 + tg * 2;
            *(float2*)(Cp + (size_t)row0 * Nb + col) =
                make_float2(acc[mi][ni][0], acc[mi][ni][1]);
            *(float2*)(Cp + (size_t)(row0 + 8) * Nb + col) =
                make_float2(acc[mi][ni][2], acc[mi][ni][3]);
        }
    }
}

// ---------------------------------------------------------------------------
// RoPE (in place). X: (MTOK, nheads, 64).
// ---------------------------------------------------------------------------
__global__ void rope_kernel(float* __restrict__ X,
                            const float* __restrict__ cosT,
                            const float* __restrict__ sinT,
                            int nheads)
{
    int idx = blockIdx.x * blockDim.x + threadIdx.x;
    int total = MTOK * nheads * 32;
    if (idx >= total) return;
    int d  = idx & 31;
    int hh = (idx >> 5) % nheads;
    int t  = idx / (32 * nheads);
    int s  = t & (S_ - 1);

    float c  = __ldg(cosT + s * HD_ + d);
    float sn = __ldg(sinT + s * HD_ + d);

    float* base = X + ((size_t)t * nheads + hh) * HD_;
    float x0 = base[d];
    float x1 = base[d + 32];
    base[d]      = x0 * c - x1 * sn;
    base[d + 32] = x1 * c + x0 * sn;
}

// ---------------------------------------------------------------------------
// Tensor-core (tf32) flash attention, causal GQA.
// grid=(S/64, HQ, B), 128 threads (4 warps). Each warp owns 16 q rows.
// KP buffer: holds K^T [d][key] during QK^T, then P [key][q] during PV.
// Vs buffer: V [key][d]. Stride 72 (== 8 mod 32) -> conflict-free fragments.
// ---------------------------------------------------------------------------
#define PSTR 72

__global__ __launch_bounds__(128)
void attn_mma_kernel(const float* __restrict__ Q, const float* __restrict__ K,
                     const float* __restrict__ V, float* __restrict__ O)
{
    __shared__ unsigned KP[64][PSTR];
    __shared__ unsigned Vs[64][PSTR];

    const int qb  = blockIdx.x;
    const int h   = blockIdx.y;
    const int b   = blockIdx.z;
    const int kvh = h >> 2;
    const int tid = threadIdx.x;
    const int wid = tid >> 5;
    const int lane = tid & 31;
    const int g    = lane >> 2;     // 0..7
    const int tg   = lane & 3;      // 0..3
    const int qrow0 = wid * 16;

    const float scale = 0.125f;

    // --- Stage Q transposed into KP, then pull fragments ---
    {
        const int dq = tid & 15;    // float4 index along d
        const int r0 = tid >> 4;    // 0..7
        #pragma unroll
        for (int j = 0; j < 8; j++) {
            int qr  = r0 + j * 8;
            int tok = b * S_ + qb * 64 + qr;
            float4 v4 = *(const float4*)(Q + (size_t)tok * HID_ + h * HD_ + dq * 4);
            KP[dq * 4 + 0][qr] = f2tf32(v4.x);
            KP[dq * 4 + 1][qr] = f2tf32(v4.y);
            KP[dq * 4 + 2][qr] = f2tf32(v4.z);
            KP[dq * 4 + 3][qr] = f2tf32(v4.w);
        }
    }
    __syncthreads();
    unsigned qfr[8][4];
    #pragma unroll
    for (int kc = 0; kc < 8; kc++) {
        qfr[kc][0] = KP[kc * 8 + tg    ][qrow0 + g];
        qfr[kc][1] = KP[kc * 8 + tg    ][qrow0 + g + 8];
        qfr[kc][2] = KP[kc * 8 + tg + 4][qrow0 + g];
        qfr[kc][3] = KP[kc * 8 + tg + 4][qrow0 + g + 8];
    }
    __syncthreads();

    float oacc[8][4];
    #pragma unroll
    for (int nt = 0; nt < 8; nt++)
        #pragma unroll
        for (int c = 0; c < 4; c++) oacc[nt][c] = 0.f;
    float m0 = -1e30f, m1 = -1e30f, l0 = 0.f, l1 = 0.f;

    const int qg0 = qb * 64 + qrow0 + g;
    const int qg1 = qg0 + 8;

    for (int kb = 0; kb <= qb; kb++) {
        // Stage K^T into KP and V into Vs (coalesced along d)
        {
            const int dq = tid & 15;
            const int r0 = tid >> 4;
            #pragma unroll
            for (int j = 0; j < 8; j++) {
                int kr  = r0 + j * 8;
                size_t base = ((size_t)(b * S_ + kb * 64 + kr) * HKV_ + kvh) * HD_ + dq * 4;
                float4 k4 = *(const float4*)(K + base);
                KP[dq * 4 + 0][kr] = f2tf32(k4.x);
                KP[dq * 4 + 1][kr] = f2tf32(k4.y);
                KP[dq * 4 + 2][kr] = f2tf32(k4.z);
                KP[dq * 4 + 3][kr] = f2tf32(k4.w);
                float4 v4 = *(const float4*)(V + base);
                uint4 u;
                u.x = f2tf32(v4.x); u.y = f2tf32(v4.y);
                u.z = f2tf32(v4.z); u.w = f2tf32(v4.w);
                *(uint4*)&Vs[kr][dq * 4] = u;
            }
        }
        __syncthreads();

        // Scores: S = Q @ K^T
        float sc[8][4];
        #pragma unroll
        for (int nt = 0; nt < 8; nt++) {
            sc[nt][0] = sc[nt][1] = sc[nt][2] = sc[nt][3] = 0.f;
            #pragma unroll
            for (int kc = 0; kc < 8; kc++) {
                unsigned b0 = KP[kc * 8 + tg    ][nt * 8 + g];
                unsigned b1 = KP[kc * 8 + tg + 4][nt * 8 + g];
                MMA_TF32(sc[nt], qfr[kc], b0, b1);
            }
        }

        // Scale + causal mask (only binds on diagonal block)
        const int kbase = kb * 64;
        #pragma unroll
        for (int nt = 0; nt < 8; nt++) {
            int key0 = kbase + nt * 8 + 2 * tg;
            sc[nt][0] = (key0     > qg0) ? -1e30f : sc[nt][0] * scale;
            sc[nt][1] = (key0 + 1 > qg0) ? -1e30f : sc[nt][1] * scale;
            sc[nt][2] = (key0     > qg1) ? -1e30f : sc[nt][2] * scale;
            sc[nt][3] = (key0 + 1 > qg1) ? -1e30f : sc[nt][3] * scale;
        }

        // Row max (reduce over 4 lanes sharing a row)
        float mx0 = -1e30f, mx1 = -1e30f;
        #pragma unroll
        for (int nt = 0; nt < 8; nt++) {
            mx0 = fmaxf(mx0, fmaxf(sc[nt][0], sc[nt][1]));
            mx1 = fmaxf(mx1, fmaxf(sc[nt][2], sc[nt][3]));
        }
        mx0 = fmaxf(mx0, __shfl_xor_sync(0xffffffffu, mx0, 1));
        mx0 = fmaxf(mx0, __shfl_xor_sync(0xffffffffu, mx0, 2));
        mx1 = fmaxf(mx1, __shfl_xor_sync(0xffffffffu, mx1, 1));
        mx1 = fmaxf(mx1, __shfl_xor_sync(0xffffffffu, mx1, 2));

        float mn0 = fmaxf(m0, mx0), mn1 = fmaxf(m1, mx1);
        float cr0 = __expf(m0 - mn0), cr1 = __expf(m1 - mn1);
        l0 *= cr0; l1 *= cr1;
        #pragma unroll
        for (int nt = 0; nt < 8; nt++) {
            oacc[nt][0] *= cr0; oacc[nt][1] *= cr0;
            oacc[nt][2] *= cr1; oacc[nt][3] *= cr1;
        }
        m0 = mn0; m1 = mn1;

        __syncthreads();   // all warps done reading K from KP

        // P = exp(S - m), store into KP as [key][q]
        #pragma unroll
        for (int nt = 0; nt < 8; nt++) {
            float p00 = __expf(sc[nt][0] - m0);
            float p01 = __expf(sc[nt][1] - m0);
            float p10 = __expf(sc[nt][2] - m1);
            float p11 = __expf(sc[nt][3] - m1);
            l0 += p00 + p01;
            l1 += p10 + p11;
            int kl = nt * 8 + 2 * tg;
            KP[kl    ][qrow0 + g    ] = f2tf32(p00);
            KP[kl + 1][qrow0 + g    ] = f2tf32(p01);
            KP[kl    ][qrow0 + g + 8] = f2tf32(p10);
            KP[kl + 1][qrow0 + g + 8] = f2tf32(p11);
        }
        __syncwarp();      // PV reads only this warp's own q-columns

        // O += P @ V
        #pragma unroll
        for (int kc = 0; kc < 8; kc++) {
            unsigned afr[4];
            afr[0] = KP[kc * 8 + tg    ][qrow0 + g];
            afr[1] = KP[kc * 8 + tg    ][qrow0 + g + 8];
            afr[2] = KP[kc * 8 + tg + 4][qrow0 + g];
            afr[3] = KP[kc * 8 + tg + 4][qrow0 + g + 8];
            #pragma unroll
            for (int nt = 0; nt < 8; nt++) {
                unsigned b0 = Vs[kc * 8 + tg    ][nt * 8 + g];
                unsigned b1 = Vs[kc * 8 + tg + 4][nt * 8 + g];
                MMA_TF32(oacc[nt], afr, b0, b1);
            }
        }
        __syncthreads();   // before restaging K/V (or exit)
    }

    // Final normalize + write
    l0 += __shfl_xor_sync(0xffffffffu, l0, 1);
    l0 += __shfl_xor_sync(0xffffffffu, l0, 2);
    l1 += __shfl_xor_sync(0xffffffffu, l1, 1);
    l1 += __shfl_xor_sync(0xffffffffu, l1, 2);
    float inv0 = 1.f / l0, inv1 = 1.f / l1;

    const size_t tok0 = (size_t)(b * S_ + qb * 64 + qrow0 + g);
    const size_t tok1 = tok0 + 8;
    #pragma unroll
    for (int nt = 0; nt < 8; nt++) {
        int col = h * HD_ + nt * 8 + 2 * tg;
        *(float2*)(O + tok0 * HID_ + col) =
            make_float2(oacc[nt][0] * inv0, oacc[nt][1] * inv0);
        *(float2*)(O + tok1 * HID_ + col) =
            make_float2(oacc[nt][2] * inv1, oacc[nt][3] * inv1);
    }
}

// ---------------------------------------------------------------------------
// Launch
// ---------------------------------------------------------------------------
extern "C" void kernel_launch(void* const* d_in, const int* in_sizes, int n_in,
                              void* d_out, int out_size)
{
    const float* hid  = (const float*)d_in[0];
    const float* cosT = (const float*)d_in[1];
    const float* sinT = (const float*)d_in[2];
    const float* Wq   = (const float*)d_in[3];
    const float* Wk   = (const float*)d_in[4];
    const float* Wv   = (const float*)d_in[5];
    const float* Wo   = (const float*)d_in[6];
    float* out = (float*)d_out;

    float *q_p, *k_p, *v_p, *attn_p;
    cudaGetSymbolAddress((void**)&q_p,    g_q);
    cudaGetSymbolAddress((void**)&k_p,    g_k);
    cudaGetSymbolAddress((void**)&v_p,    g_v);
    cudaGetSymbolAddress((void**)&attn_p, g_attn);

    // Fused QKV projection (tf32 tensor cores)
    {
        dim3 g(24, 16);
        mma_gemm_qkv<<<g, 256>>>(hid, Wq, Wk, Wv, q_p, k_p, v_p);
    }

    // RoPE
    {
        int totq = MTOK * HQ_ * 32;
        rope_kernel<<<(totq + 255) / 256, 256>>>(q_p, cosT, sinT, HQ_);
        int totk = MTOK * HKV_ * 32;
        rope_kernel<<<(totk + 255) / 256, 256>>>(k_p, cosT, sinT, HKV_);
    }

    // Attention (tf32 tensor cores)
    {
        dim3 ga(S_ / 64, HQ_, B_);
        attn_mma_kernel<<<ga, 128>>>(q_p, k_p, v_p, attn_p);
    }

    // Output projection
    {
        dim3 go(16, 16);
        mma_gemm_qkv<<<go, 256>>>(attn_p, Wo, Wo, Wo, out, out, out);
    }
}